// round 14
// baseline (speedup 1.0000x reference)
#include <cuda_runtime.h>
#include <cuda_bf16.h>
#include <cstdint>

constexpr int Bc = 8, Hc = 16, Mc = 1024, Nc = 1024, Dc = 64;
constexpr int BHc = Bc * Hc;
constexpr long long OUT_ELEMS = (long long)BHc * Mc * Dc;
constexpr long long P_ELEMS   = (long long)BHc * Mc * Nc;

constexpr int MT = 32;        // M rows per CTA
constexpr int NT = 128;       // tile depth
constexpr int THREADS = 256;  // 8 warps, 4 CTAs/SM

// ---- fragment-layout scratch, uint4-packed (shared by 32 CTAs per bh) ----
// KS slot = ((nbg*4 + kc)*32 + lane) : {h0, h1, l0, l1} bf16x2 pairs
// VS slot = ((kqkc*4 + db2)*32 + lane) : {vh0[2*db2], vh1[2*db2], vh0[2*db2+1], vh1[2*db2+1]} tf32
__device__ uint4 KSg[(size_t)BHc * 8 * 2048];   // 32 MB
__device__ uint4 VSg[(size_t)BHc * 8 * 2048];   // 32 MB

// ---- main-kernel smem (bytes) ----
constexpr int QH_OFF = 0;        // Q staging hi plane [32][72] bf16 (pitch 144B), transient
constexpr int QL_OFF = 4608;
constexpr int P_OFF  = 0;        // phase 3: P block [32][132] f32 (aliases Q region)
constexpr int RED_OFF = 0;       // epilogue reduce (aliases P)
constexpr int MSK_OFF = 24576;   // int[1024]
constexpr int SMEM_BYTES = 28672;

#define NEG_INF_F (-1e9f)

__device__ __forceinline__ uint32_t pack2(float a, float b) {   // a -> low half
    uint32_t r; asm("cvt.rn.bf16x2.f32 %0, %1, %2;" : "=r"(r) : "f"(b), "f"(a)); return r;
}
__device__ __forceinline__ float bfr(float x) { return __bfloat162float(__float2bfloat16_rn(x)); }
__device__ __forceinline__ void store_hilo(char* sm, int ho, int lo, uint32_t byte, float4 v) {
    uint2 h = make_uint2(pack2(v.x, v.y), pack2(v.z, v.w));
    uint2 l = make_uint2(pack2(v.x - bfr(v.x), v.y - bfr(v.y)),
                         pack2(v.z - bfr(v.z), v.w - bfr(v.w)));
    *(uint2*)(sm + ho + byte) = h;
    *(uint2*)(sm + lo + byte) = l;
}
__device__ __forceinline__ void mma_bf16(float* c, const uint32_t* a, uint32_t b0, uint32_t b1) {
    asm volatile("mma.sync.aligned.m16n8k16.row.col.f32.bf16.bf16.f32 "
        "{%0,%1,%2,%3}, {%4,%5,%6,%7}, {%8,%9}, {%0,%1,%2,%3};\n"
        : "+f"(c[0]), "+f"(c[1]), "+f"(c[2]), "+f"(c[3])
        : "r"(a[0]), "r"(a[1]), "r"(a[2]), "r"(a[3]), "r"(b0), "r"(b1));
}
__device__ __forceinline__ uint32_t tf32_hi(float x) {
    uint32_t h; asm("cvt.rna.tf32.f32 %0, %1;" : "=r"(h) : "f"(x)); return h;
}
__device__ __forceinline__ void tf32_split(float x, uint32_t& h, uint32_t& l) {
    asm("cvt.rna.tf32.f32 %0, %1;" : "=r"(h) : "f"(x));
    float r = x - __uint_as_float(h);
    asm("cvt.rna.tf32.f32 %0, %1;" : "=r"(l) : "f"(r));
}
__device__ __forceinline__ void mma_tf32(float* c, const uint32_t* a, uint32_t b0, uint32_t b1) {
    asm volatile("mma.sync.aligned.m16n8k8.row.col.f32.tf32.tf32.f32 "
        "{%0,%1,%2,%3}, {%4,%5,%6,%7}, {%8,%9}, {%0,%1,%2,%3};\n"
        : "+f"(c[0]), "+f"(c[1]), "+f"(c[2]), "+f"(c[3])
        : "r"(a[0]), "r"(a[1]), "r"(a[2]), "r"(a[3]), "r"(b0), "r"(b1));
}

// =================== prep: K/V -> packed fragment scratch ===================
__global__ __launch_bounds__(256)
void prep_kernel(const float* __restrict__ k, const float* __restrict__ v)
{
    __shared__ float KT[128 * 68];
    const int bhnt = blockIdx.x;            // bh*8 + nt
    const int bh = bhnt >> 3, nt = bhnt & 7;
    const int tid = threadIdx.x;

    // ---- K tile -> KS ----
    {
        const float4* kg = (const float4*)(k + ((size_t)bh * Nc + nt * NT) * Dc);
        #pragma unroll
        for (int i = 0; i < 8; i++) {
            int f4 = i * 256 + tid;
            float4 val = kg[f4];
            *(float4*)(KT + (f4 >> 4) * 68 + (f4 & 15) * 4) = val;
        }
    }
    __syncthreads();
    {
        uint4* ks = KSg + (size_t)bhnt * 2048;
        #pragma unroll
        for (int i = 0; i < 8; i++) {
            int slot = i * 256 + tid;
            int l = slot & 31, idx = slot >> 5;       // idx = nbg*4 + kc
            int nbg = idx >> 2, kc = idx & 3;
            int n = nbg * 8 + (l >> 2), k0 = kc * 16 + 2 * (l & 3);
            float x0 = KT[n * 68 + k0],     x1 = KT[n * 68 + k0 + 1];
            float y0 = KT[n * 68 + k0 + 8], y1 = KT[n * 68 + k0 + 9];
            ks[slot] = make_uint4(pack2(x0, x1), pack2(y0, y1),
                                  pack2(x0 - bfr(x0), x1 - bfr(x1)),
                                  pack2(y0 - bfr(y0), y1 - bfr(y1)));
        }
    }
    __syncthreads();
    // ---- V tile -> VS ----
    {
        const float4* vg = (const float4*)(v + ((size_t)bh * Nc + nt * NT) * Dc);
        #pragma unroll
        for (int i = 0; i < 8; i++) {
            int f4 = i * 256 + tid;
            float4 val = vg[f4];
            *(float4*)(KT + (f4 >> 4) * 68 + (f4 & 15) * 4) = val;
        }
    }
    __syncthreads();
    {
        uint4* vs = VSg + (size_t)bhnt * 2048;
        #pragma unroll
        for (int i = 0; i < 8; i++) {
            int slot = i * 256 + tid;
            int l = slot & 31, idx = slot >> 5;       // idx = kqkc*4 + db2
            int kqkc = idx >> 2, db2 = idx & 3;
            int kk = kqkc * 8, t = l & 3;
            int d0 = db2 * 16 + (l >> 2), d1 = d0 + 8;
            vs[slot] = make_uint4(tf32_hi(KT[(kk + t) * 68 + d0]),
                                  tf32_hi(KT[(kk + t + 4) * 68 + d0]),
                                  tf32_hi(KT[(kk + t) * 68 + d1]),
                                  tf32_hi(KT[(kk + t + 4) * 68 + d1]));
        }
    }
}

// =================== main kernel ===================
__global__ __launch_bounds__(THREADS, 4)
void attn_k14(const float* __restrict__ q, const int* __restrict__ mask,
              float* __restrict__ outp, float* __restrict__ pp)
{
    extern __shared__ char sm[];
    int* Msk = (int*)(sm + MSK_OFF);

    const int bh = blockIdx.x >> 5;
    const int m0 = (blockIdx.x & 31) * MT;
    const int tid = threadIdx.x, wid = tid >> 5, lane = tid & 31;
    const int g = lane >> 2, t = lane & 3;
    const float scale = 1.0f / 32.0f;   // 1/sqrt(N=1024), faithful to source bug
    float* Sbase = pp + ((size_t)bh * Mc + m0) * Nc;

    #pragma unroll
    for (int i = 0; i < Nc / THREADS; i++)
        Msk[i * THREADS + tid] = mask[(size_t)bh * Nc + i * THREADS + tid];

    {   // stage Q -> bf16 hi/lo planes (pitch 144 B), transient
        const float4* qg = (const float4*)(q + (size_t)(bh * Mc + m0) * Dc);
        #pragma unroll
        for (int i = 0; i < 2; i++) {
            int f4 = i * THREADS + tid;
            float4 val = qg[f4];
            store_hilo(sm, QH_OFF, QL_OFF, (uint32_t)((f4 >> 4) * 144 + (f4 & 15) * 8), val);
        }
    }
    __syncthreads();

    // hoist Q fragments (hi+lo) to registers
    const int mi = wid & 1, nbp = wid >> 1;
    uint32_t ah[4][4], al[4][4];
    #pragma unroll
    for (int kc = 0; kc < 4; kc++) {
        uint32_t base = (uint32_t)((mi * 16 + g) * 144 + kc * 32 + 4 * t);
        ah[kc][0] = *(uint32_t*)(sm + QH_OFF + base);
        ah[kc][1] = *(uint32_t*)(sm + QH_OFF + base + 8 * 144);
        ah[kc][2] = *(uint32_t*)(sm + QH_OFF + base + 16);
        ah[kc][3] = *(uint32_t*)(sm + QH_OFF + base + 8 * 144 + 16);
        al[kc][0] = *(uint32_t*)(sm + QL_OFF + base);
        al[kc][1] = *(uint32_t*)(sm + QL_OFF + base + 8 * 144);
        al[kc][2] = *(uint32_t*)(sm + QL_OFF + base + 16);
        al[kc][3] = *(uint32_t*)(sm + QL_OFF + base + 8 * 144 + 16);
    }
    __syncthreads();   // Q region free for phase-3 reuse

    // ============ phase 1: S = mask(scale(Q K^T)), bf16 3-term, NO syncs ============
    const uint4* ksb = KSg + (size_t)(bh * 8) * 2048;
    #pragma unroll 1
    for (int nt = 0; nt < Nc / NT; nt++) {
        const uint4* kst = ksb + nt * 2048;
        float acc[4][4] = {};
        #pragma unroll
        for (int kc = 0; kc < 4; kc++) {
            #pragma unroll
            for (int nb = 0; nb < 4; nb++) {
                uint4 kf = kst[((nbp * 4 + nb) * 4 + kc) * 32 + lane];
                mma_bf16(acc[nb], ah[kc], kf.x, kf.y);   // qh*kh
                mma_bf16(acc[nb], al[kc], kf.x, kf.y);   // ql*kh
                mma_bf16(acc[nb], ah[kc], kf.z, kf.w);   // qh*kl
            }
        }
        #pragma unroll
        for (int nb = 0; nb < 4; nb++) {
            const int m = mi * 16 + g;
            const int n = nt * NT + nbp * 32 + nb * 8 + 2 * t;
            const bool ok0 = Msk[n] != 0, ok1 = Msk[n + 1] != 0;
            *(float2*)(Sbase + (size_t)m * Nc + n) = make_float2(
                ok0 ? acc[nb][0] * scale : NEG_INF_F, ok1 ? acc[nb][1] * scale : NEG_INF_F);
            *(float2*)(Sbase + (size_t)(m + 8) * Nc + n) = make_float2(
                ok0 ? acc[nb][2] * scale : NEG_INF_F, ok1 ? acc[nb][3] * scale : NEG_INF_F);
        }
    }
    __syncthreads();

    // ============ phase 2: register softmax (rows L2-hot) ============
    #pragma unroll 1
    for (int rr = 0; rr < 4; rr++) {
        const int m = wid * 4 + rr;
        float* prow = Sbase + (size_t)m * Nc;
        float r[32], mx = NEG_INF_F;
        #pragma unroll
        for (int i = 0; i < 32; i++) { r[i] = prow[i * 32 + lane]; mx = fmaxf(mx, r[i]); }
        #pragma unroll
        for (int o = 16; o; o >>= 1) mx = fmaxf(mx, __shfl_xor_sync(0xffffffffu, mx, o));
        float s = 0.0f;
        #pragma unroll
        for (int i = 0; i < 32; i++) { r[i] = __expf(r[i] - mx); s += r[i]; }
        #pragma unroll
        for (int o = 16; o; o >>= 1) s += __shfl_xor_sync(0xffffffffu, s, o);
        const float inv = 1.0f / s;
        #pragma unroll
        for (int i = 0; i < 32; i++) prow[i * 32 + lane] = r[i] * inv;
    }
    __syncthreads();

    // ============ phase 3: out = P V, tf32 2-term, k-quarter split ============
    const int mi3 = wid & 1, kq = wid >> 1;
    float* Pf = (float*)(sm + P_OFF);
    const uint4* vsb = VSg + (size_t)(bh * 8) * 2048;

    float oacc[8][4] = {};
    #pragma unroll 1
    for (int nt = 0; nt < Nc / NT; nt++) {
        __syncthreads();
        {   // stage P block [32][128] f32 pitch 132 (coalesced L2 reads)
            #pragma unroll
            for (int i = 0; i < 4; i++) {
                int f4 = i * THREADS + tid;
                int row = f4 >> 5, c = (f4 & 31) * 4;
                float4 val = *(const float4*)(Sbase + (size_t)row * Nc + nt * NT + c);
                *(float4*)(Pf + row * 132 + c) = val;
            }
        }
        __syncthreads();

        const uint4* vst = vsb + nt * 2048;
        #pragma unroll
        for (int kc = 0; kc < 4; kc++) {
            const int kk = kq * 32 + kc * 8;
            const float* pb = Pf + (mi3 * 16 + g) * 132 + kk;
            uint32_t pah[4], pal[4];
            tf32_split(pb[t],               pah[0], pal[0]);
            tf32_split(pb[8 * 132 + t],     pah[1], pal[1]);
            tf32_split(pb[t + 4],           pah[2], pal[2]);
            tf32_split(pb[8 * 132 + t + 4], pah[3], pal[3]);
            #pragma unroll
            for (int db2 = 0; db2 < 4; db2++) {
                uint4 vv = vst[(((kq * 4 + kc) * 4) + db2) * 32 + lane];
                mma_tf32(oacc[2 * db2],     pah, vv.x, vv.y);
                mma_tf32(oacc[2 * db2],     pal, vv.x, vv.y);
                mma_tf32(oacc[2 * db2 + 1], pah, vv.z, vv.w);
                mma_tf32(oacc[2 * db2 + 1], pal, vv.z, vv.w);
            }
        }
    }
    __syncthreads();
    // k-quarter reduce through Red (aliases P region; dead now)
    float* Red = (float*)(sm + RED_OFF);
    if (kq != 0) {
        #pragma unroll
        for (int db = 0; db < 8; db++)
            *(float4*)(&Red[((mi3 * 3 + (kq - 1)) * 8 + db) * 128 + lane * 4]) =
                make_float4(oacc[db][0], oacc[db][1], oacc[db][2], oacc[db][3]);
    }
    __syncthreads();
    if (kq == 0 && outp) {
        #pragma unroll
        for (int db = 0; db < 8; db++) {
            float4 r1 = *(float4*)(&Red[((mi3 * 3 + 0) * 8 + db) * 128 + lane * 4]);
            float4 r2 = *(float4*)(&Red[((mi3 * 3 + 1) * 8 + db) * 128 + lane * 4]);
            float4 r3 = *(float4*)(&Red[((mi3 * 3 + 2) * 8 + db) * 128 + lane * 4]);
            const int m = mi3 * 16 + g;
            float* ob = outp + ((size_t)bh * Mc + m0 + m) * Dc + db * 8 + 2 * t;
            *(float2*)ob = make_float2(oacc[db][0] + r1.x + r2.x + r3.x,
                                       oacc[db][1] + r1.y + r2.y + r3.y);
            *(float2*)(ob + 8 * Dc) = make_float2(oacc[db][2] + r1.z + r2.z + r3.z,
                                                  oacc[db][3] + r1.w + r2.w + r3.w);
        }
    }
}

extern "C" void kernel_launch(void* const* d_in, const int* in_sizes, int n_in,
                              void* d_out, int out_size)
{
    const float* q    = (const float*)d_in[0];
    const float* k    = (const float*)d_in[1];
    const float* v    = (const float*)d_in[2];
    const int*   mask = (const int*)d_in[3];
    float* outp = nullptr;
    float* pp   = nullptr;
    long long osz = (long long)out_size;
    if (osz >= OUT_ELEMS + P_ELEMS) { outp = (float*)d_out; pp = (float*)d_out + OUT_ELEMS; }
    else                            { pp = (float*)d_out; }

    prep_kernel<<<BHc * 8, 256>>>(k, v);
    cudaFuncSetAttribute(attn_k14, cudaFuncAttributeMaxDynamicSharedMemorySize, SMEM_BYTES);
    attn_k14<<<BHc * (Mc / MT), THREADS, SMEM_BYTES>>>(q, mask, outp, pp);
}

// round 15
// speedup vs baseline: 1.2464x; 1.2464x over previous
#include <cuda_runtime.h>
#include <cuda_bf16.h>
#include <cstdint>

constexpr int Bc = 8, Hc = 16, Mc = 1024, Nc = 1024, Dc = 64;
constexpr int BHc = Bc * Hc;
constexpr long long OUT_ELEMS = (long long)BHc * Mc * Dc;
constexpr long long P_ELEMS   = (long long)BHc * Mc * Nc;

constexpr int MT = 32;        // M rows per CTA
constexpr int NT = 128;       // tile depth
constexpr int THREADS = 256;  // 8 warps, 3 CTAs/SM

// ---- fragment-layout scratch, uint4-packed (shared by 32 CTAs per bh) ----
// KS slot = ((nbg*4 + kc)*32 + lane) : {h0, h1, l0, l1} bf16x2 pairs
// VS slot = ((kqkc*4 + db2)*32 + lane) : {vh0_d0, vh1_d0, vh0_d1, vh1_d1} tf32 bits
__device__ uint4 KSg[(size_t)BHc * 8 * 2048];   // 32 MB
__device__ uint4 VSg[(size_t)BHc * 8 * 2048];   // 32 MB

// ---- main-kernel smem (bytes) ----
constexpr int QH_OFF = 0;        // Q staging hi plane [32][72] bf16 (pitch 144B), transient
constexpr int QL_OFF = 4608;
constexpr int P_OFF  = 0;        // phase 3: P block [32][132] f32 (aliases Q region)
constexpr int RED_OFF = 0;       // epilogue reduce (aliases P)
constexpr int MSK_OFF = 24576;   // int[1024]
constexpr int SMEM_BYTES = 28672;

#define NEG_INF_F (-1e9f)

__device__ __forceinline__ uint32_t pack2(float a, float b) {   // a -> low half
    uint32_t r; asm("cvt.rn.bf16x2.f32 %0, %1, %2;" : "=r"(r) : "f"(b), "f"(a)); return r;
}
__device__ __forceinline__ float bfr(float x) { return __bfloat162float(__float2bfloat16_rn(x)); }
__device__ __forceinline__ void store_hilo(char* sm, int ho, int lo, uint32_t byte, float4 v) {
    uint2 h = make_uint2(pack2(v.x, v.y), pack2(v.z, v.w));
    uint2 l = make_uint2(pack2(v.x - bfr(v.x), v.y - bfr(v.y)),
                         pack2(v.z - bfr(v.z), v.w - bfr(v.w)));
    *(uint2*)(sm + ho + byte) = h;
    *(uint2*)(sm + lo + byte) = l;
}
__device__ __forceinline__ void mma_bf16(float* c, const uint32_t* a, uint32_t b0, uint32_t b1) {
    asm volatile("mma.sync.aligned.m16n8k16.row.col.f32.bf16.bf16.f32 "
        "{%0,%1,%2,%3}, {%4,%5,%6,%7}, {%8,%9}, {%0,%1,%2,%3};\n"
        : "+f"(c[0]), "+f"(c[1]), "+f"(c[2]), "+f"(c[3])
        : "r"(a[0]), "r"(a[1]), "r"(a[2]), "r"(a[3]), "r"(b0), "r"(b1));
}
__device__ __forceinline__ uint32_t tf32_hi(float x) {
    uint32_t h; asm("cvt.rna.tf32.f32 %0, %1;" : "=r"(h) : "f"(x)); return h;
}
__device__ __forceinline__ void tf32_split(float x, uint32_t& h, uint32_t& l) {
    asm("cvt.rna.tf32.f32 %0, %1;" : "=r"(h) : "f"(x));
    float r = x - __uint_as_float(h);
    asm("cvt.rna.tf32.f32 %0, %1;" : "=r"(l) : "f"(r));
}
__device__ __forceinline__ void mma_tf32(float* c, const uint32_t* a, uint32_t b0, uint32_t b1) {
    asm volatile("mma.sync.aligned.m16n8k8.row.col.f32.tf32.tf32.f32 "
        "{%0,%1,%2,%3}, {%4,%5,%6,%7}, {%8,%9}, {%0,%1,%2,%3};\n"
        : "+f"(c[0]), "+f"(c[1]), "+f"(c[2]), "+f"(c[3])
        : "r"(a[0]), "r"(a[1]), "r"(a[2]), "r"(a[3]), "r"(b0), "r"(b1));
}

// =================== prep: K/V -> packed fragment scratch ===================
__global__ __launch_bounds__(256)
void prep_kernel(const float* __restrict__ k, const float* __restrict__ v)
{
    __shared__ float KT[128 * 68];
    const int bhnt = blockIdx.x;            // bh*8 + nt
    const int bh = bhnt >> 3, nt = bhnt & 7;
    const int tid = threadIdx.x;

    // ---- K tile -> KS ----
    {
        const float4* kg = (const float4*)(k + ((size_t)bh * Nc + nt * NT) * Dc);
        #pragma unroll
        for (int i = 0; i < 8; i++) {
            int f4 = i * 256 + tid;
            float4 val = kg[f4];
            *(float4*)(KT + (f4 >> 4) * 68 + (f4 & 15) * 4) = val;
        }
    }
    __syncthreads();
    {
        uint4* ks = KSg + (size_t)bhnt * 2048;
        #pragma unroll
        for (int i = 0; i < 8; i++) {
            int slot = i * 256 + tid;
            int l = slot & 31, idx = slot >> 5;       // idx = nbg*4 + kc
            int nbg = idx >> 2, kc = idx & 3;
            int n = nbg * 8 + (l >> 2), k0 = kc * 16 + 2 * (l & 3);
            float x0 = KT[n * 68 + k0],     x1 = KT[n * 68 + k0 + 1];
            float y0 = KT[n * 68 + k0 + 8], y1 = KT[n * 68 + k0 + 9];
            ks[slot] = make_uint4(pack2(x0, x1), pack2(y0, y1),
                                  pack2(x0 - bfr(x0), x1 - bfr(x1)),
                                  pack2(y0 - bfr(y0), y1 - bfr(y1)));
        }
    }
    __syncthreads();
    // ---- V tile -> VS ----
    {
        const float4* vg = (const float4*)(v + ((size_t)bh * Nc + nt * NT) * Dc);
        #pragma unroll
        for (int i = 0; i < 8; i++) {
            int f4 = i * 256 + tid;
            float4 val = vg[f4];
            *(float4*)(KT + (f4 >> 4) * 68 + (f4 & 15) * 4) = val;
        }
    }
    __syncthreads();
    {
        uint4* vs = VSg + (size_t)bhnt * 2048;
        #pragma unroll
        for (int i = 0; i < 8; i++) {
            int slot = i * 256 + tid;
            int l = slot & 31, idx = slot >> 5;       // idx = kqkc*4 + db2
            int kqkc = idx >> 2, db2 = idx & 3;
            int kk = kqkc * 8, t = l & 3;
            int d0 = db2 * 16 + (l >> 2), d1 = d0 + 8;
            vs[slot] = make_uint4(tf32_hi(KT[(kk + t) * 68 + d0]),
                                  tf32_hi(KT[(kk + t + 4) * 68 + d0]),
                                  tf32_hi(KT[(kk + t) * 68 + d1]),
                                  tf32_hi(KT[(kk + t + 4) * 68 + d1]));
        }
    }
}

// =================== main kernel ===================
__global__ __launch_bounds__(THREADS, 3)
void attn_k15(const float* __restrict__ q, const int* __restrict__ mask,
              float* __restrict__ outp, float* __restrict__ pp)
{
    extern __shared__ char sm[];
    int* Msk = (int*)(sm + MSK_OFF);

    const int bh = blockIdx.x >> 5;
    const int m0 = (blockIdx.x & 31) * MT;
    const int tid = threadIdx.x, wid = tid >> 5, lane = tid & 31;
    const int g = lane >> 2, t = lane & 3;
    const float scale = 1.0f / 32.0f;   // 1/sqrt(N=1024), faithful to source bug
    float* Sbase = pp + ((size_t)bh * Mc + m0) * Nc;

    #pragma unroll
    for (int i = 0; i < Nc / THREADS; i++)
        Msk[i * THREADS + tid] = mask[(size_t)bh * Nc + i * THREADS + tid];

    {   // stage Q -> bf16 hi/lo planes (pitch 144 B), transient
        const float4* qg = (const float4*)(q + (size_t)(bh * Mc + m0) * Dc);
        #pragma unroll
        for (int i = 0; i < 2; i++) {
            int f4 = i * THREADS + tid;
            float4 val = qg[f4];
            store_hilo(sm, QH_OFF, QL_OFF, (uint32_t)((f4 >> 4) * 144 + (f4 & 15) * 8), val);
        }
    }
    __syncthreads();

    // hoist Q fragments (hi+lo) to registers
    const int mi = wid & 1, nbp = wid >> 1;
    uint32_t ah[4][4], al[4][4];
    #pragma unroll
    for (int kc = 0; kc < 4; kc++) {
        uint32_t base = (uint32_t)((mi * 16 + g) * 144 + kc * 32 + 4 * t);
        ah[kc][0] = *(uint32_t*)(sm + QH_OFF + base);
        ah[kc][1] = *(uint32_t*)(sm + QH_OFF + base + 8 * 144);
        ah[kc][2] = *(uint32_t*)(sm + QH_OFF + base + 16);
        ah[kc][3] = *(uint32_t*)(sm + QH_OFF + base + 8 * 144 + 16);
        al[kc][0] = *(uint32_t*)(sm + QL_OFF + base);
        al[kc][1] = *(uint32_t*)(sm + QL_OFF + base + 8 * 144);
        al[kc][2] = *(uint32_t*)(sm + QL_OFF + base + 16);
        al[kc][3] = *(uint32_t*)(sm + QL_OFF + base + 8 * 144 + 16);
    }
    __syncthreads();   // Q region free for phase-3 reuse

    // ============ phase 1: S = mask(scale(Q K^T)), bf16 3-term, NO syncs ============
    const uint4* ksb = KSg + (size_t)(bh * 8) * 2048;
    #pragma unroll 1
    for (int nt = 0; nt < Nc / NT; nt++) {
        const uint4* kst = ksb + nt * 2048;
        float acc[4][4] = {};
        #pragma unroll
        for (int kc = 0; kc < 4; kc++) {
            #pragma unroll
            for (int nb = 0; nb < 4; nb++) {
                uint4 kf = kst[((nbp * 4 + nb) * 4 + kc) * 32 + lane];
                mma_bf16(acc[nb], ah[kc], kf.x, kf.y);   // qh*kh
                mma_bf16(acc[nb], al[kc], kf.x, kf.y);   // ql*kh
                mma_bf16(acc[nb], ah[kc], kf.z, kf.w);   // qh*kl
            }
        }
        #pragma unroll
        for (int nb = 0; nb < 4; nb++) {
            const int m = mi * 16 + g;
            const int n = nt * NT + nbp * 32 + nb * 8 + 2 * t;
            const bool ok0 = Msk[n] != 0, ok1 = Msk[n + 1] != 0;
            *(float2*)(Sbase + (size_t)m * Nc + n) = make_float2(
                ok0 ? acc[nb][0] * scale : NEG_INF_F, ok1 ? acc[nb][1] * scale : NEG_INF_F);
            *(float2*)(Sbase + (size_t)(m + 8) * Nc + n) = make_float2(
                ok0 ? acc[nb][2] * scale : NEG_INF_F, ok1 ? acc[nb][3] * scale : NEG_INF_F);
        }
    }
    __syncthreads();

    // ============ phase 2: register softmax (rows L2-hot) ============
    #pragma unroll 1
    for (int rr = 0; rr < 4; rr++) {
        const int m = wid * 4 + rr;
        float* prow = Sbase + (size_t)m * Nc;
        float r[32], mx = NEG_INF_F;
        #pragma unroll
        for (int i = 0; i < 32; i++) { r[i] = prow[i * 32 + lane]; mx = fmaxf(mx, r[i]); }
        #pragma unroll
        for (int o = 16; o; o >>= 1) mx = fmaxf(mx, __shfl_xor_sync(0xffffffffu, mx, o));
        float s = 0.0f;
        #pragma unroll
        for (int i = 0; i < 32; i++) { r[i] = __expf(r[i] - mx); s += r[i]; }
        #pragma unroll
        for (int o = 16; o; o >>= 1) s += __shfl_xor_sync(0xffffffffu, s, o);
        const float inv = 1.0f / s;
        #pragma unroll
        for (int i = 0; i < 32; i++) prow[i * 32 + lane] = r[i] * inv;
    }
    __syncthreads();

    // ============ phase 3: out = P V, tf32 2-term, k-quarter split ============
    const int mi3 = wid & 1, kq = wid >> 1;
    float* Pf = (float*)(sm + P_OFF);
    const uint4* vsb = VSg + (size_t)(bh * 8) * 2048;

    float oacc[8][4] = {};
    #pragma unroll 1
    for (int nt = 0; nt < Nc / NT; nt++) {
        __syncthreads();
        {   // stage P block [32][128] f32 pitch 132 (coalesced L2 reads)
            #pragma unroll
            for (int i = 0; i < 4; i++) {
                int f4 = i * THREADS + tid;
                int row = f4 >> 5, c = (f4 & 31) * 4;
                float4 val = *(const float4*)(Sbase + (size_t)row * Nc + nt * NT + c);
                *(float4*)(Pf + row * 132 + c) = val;
            }
        }
        __syncthreads();

        const uint4* vst = vsb + nt * 2048;
        #pragma unroll
        for (int kc = 0; kc < 4; kc++) {
            const int kk = kq * 32 + kc * 8;
            const float* pb = Pf + (mi3 * 16 + g) * 132 + kk;
            uint32_t pah[4], pal[4];
            tf32_split(pb[t],               pah[0], pal[0]);
            tf32_split(pb[8 * 132 + t],     pah[1], pal[1]);
            tf32_split(pb[t + 4],           pah[2], pal[2]);
            tf32_split(pb[8 * 132 + t + 4], pah[3], pal[3]);
            #pragma unroll
            for (int db2 = 0; db2 < 4; db2++) {
                uint4 vv = vst[(((kq * 4 + kc) * 4) + db2) * 32 + lane];
                mma_tf32(oacc[2 * db2],     pah, vv.x, vv.y);
                mma_tf32(oacc[2 * db2],     pal, vv.x, vv.y);
                mma_tf32(oacc[2 * db2 + 1], pah, vv.z, vv.w);
                mma_tf32(oacc[2 * db2 + 1], pal, vv.z, vv.w);
            }
        }
    }
    __syncthreads();
    // k-quarter reduce through Red (aliases P region; dead now)
    float* Red = (float*)(sm + RED_OFF);
    if (kq != 0) {
        #pragma unroll
        for (int db = 0; db < 8; db++)
            *(float4*)(&Red[((mi3 * 3 + (kq - 1)) * 8 + db) * 128 + lane * 4]) =
                make_float4(oacc[db][0], oacc[db][1], oacc[db][2], oacc[db][3]);
    }
    __syncthreads();
    if (kq == 0 && outp) {
        #pragma unroll
        for (int db = 0; db < 8; db++) {
            float4 r1 = *(float4*)(&Red[((mi3 * 3 + 0) * 8 + db) * 128 + lane * 4]);
            float4 r2 = *(float4*)(&Red[((mi3 * 3 + 1) * 8 + db) * 128 + lane * 4]);
            float4 r3 = *(float4*)(&Red[((mi3 * 3 + 2) * 8 + db) * 128 + lane * 4]);
            const int m = mi3 * 16 + g;
            float* ob = outp + ((size_t)bh * Mc + m0 + m) * Dc + db * 8 + 2 * t;
            *(float2*)ob = make_float2(oacc[db][0] + r1.x + r2.x + r3.x,
                                       oacc[db][1] + r1.y + r2.y + r3.y);
            *(float2*)(ob + 8 * Dc) = make_float2(oacc[db][2] + r1.z + r2.z + r3.z,
                                                  oacc[db][3] + r1.w + r2.w + r3.w);
        }
    }
}

extern "C" void kernel_launch(void* const* d_in, const int* in_sizes, int n_in,
                              void* d_out, int out_size)
{
    const float* q    = (const float*)d_in[0];
    const float* k    = (const float*)d_in[1];
    const float* v    = (const float*)d_in[2];
    const int*   mask = (const int*)d_in[3];
    float* outp = nullptr;
    float* pp   = nullptr;
    long long osz = (long long)out_size;
    if (osz >= OUT_ELEMS + P_ELEMS) { outp = (float*)d_out; pp = (float*)d_out + OUT_ELEMS; }
    else                            { pp = (float*)d_out; }

    prep_kernel<<<BHc * 8, 256>>>(k, v);
    cudaFuncSetAttribute(attn_k15, cudaFuncAttributeMaxDynamicSharedMemorySize, SMEM_BYTES);
    attn_k15<<<BHc * (Mc / MT), THREADS, SMEM_BYTES>>>(q, mask, outp, pp);
}